// round 16
// baseline (speedup 1.0000x reference)
#include <cuda_runtime.h>
#include <cuda_fp16.h>
#include <math_constants.h>
#include <cstdint>

// ---------------------------------------------------------------------------
// MultiHeadAttention fp32 I/O, fp16 tensor-core compute (fp32 accumulate).
// B=2, S=2048, D=1024, H=16, Hd=64, causal.
//  Phase 0: convert (1 float4/thread, max MLP), resets ticket counters
//  Phase 1: Q/K/V = X @ W^T     (persistent fp16 GEMM, z-fast tickets)
//  Phase 2: flash attention      (persistent; f16x2 ex2 softmax -> fragments)
//  Phase 3: out = ctx @ Wo^T + b (plain fp16 GEMM)
// ---------------------------------------------------------------------------

#define B_   2
#define S_   2048
#define D_   1024
#define H_   16
#define HD_  64

__device__ __half g_Q[B_ * S_ * D_];
__device__ __half g_K[B_ * S_ * D_];
__device__ __half g_V[B_ * S_ * D_];
__device__ __half g_ctx[B_ * S_ * D_];
__device__ __half g_Xh[B_ * S_ * D_];
__device__ __half g_Wqh[D_ * D_];
__device__ __half g_Wkh[D_ * D_];
__device__ __half g_Wvh[D_ * D_];
__device__ __half g_Woh[D_ * D_];

__device__ int g_cnt_qkv;
__device__ int g_cnt_fl;

#define PERS_CTAS 296                   // 148 SMs x 2 CTAs

// --------------------------- helpers ---------------------------------------
__device__ __forceinline__ float ex2(float x) {
    float r;
    asm("ex2.approx.ftz.f32 %0, %1;" : "=f"(r) : "f"(x));
    return r;
}
__device__ __forceinline__ uint32_t packh2(float lo, float hi) {
    uint32_t d;
    asm("cvt.rn.f16x2.f32 %0, %1, %2;" : "=r"(d) : "f"(hi), "f"(lo));
    return d;
}
__device__ __forceinline__ uint32_t ex2h2(uint32_t x) {
    uint32_t r;
    asm("ex2.approx.f16x2 %0, %1;" : "=r"(r) : "r"(x));
    return r;
}
__device__ __forceinline__ void mma16(float* c, const uint32_t* a, const uint32_t* b) {
    asm volatile(
        "mma.sync.aligned.m16n8k16.row.col.f32.f16.f16.f32 "
        "{%0,%1,%2,%3}, {%4,%5,%6,%7}, {%8,%9}, {%0,%1,%2,%3};\n"
        : "+f"(c[0]), "+f"(c[1]), "+f"(c[2]), "+f"(c[3])
        : "r"(a[0]), "r"(a[1]), "r"(a[2]), "r"(a[3]), "r"(b[0]), "r"(b[1]));
}
__device__ __forceinline__ void ldm_x4(uint32_t* r, uint32_t addr) {
    asm volatile("ldmatrix.sync.aligned.m8n8.x4.shared.b16 {%0,%1,%2,%3}, [%4];"
                 : "=r"(r[0]), "=r"(r[1]), "=r"(r[2]), "=r"(r[3]) : "r"(addr));
}
__device__ __forceinline__ void ldm_x4_t(uint32_t* r, uint32_t addr) {
    asm volatile("ldmatrix.sync.aligned.m8n8.x4.trans.shared.b16 {%0,%1,%2,%3}, [%4];"
                 : "=r"(r[0]), "=r"(r[1]), "=r"(r[2]), "=r"(r[3]) : "r"(addr));
}
__device__ __forceinline__ void cpa16(void* s, const void* g) {
    uint32_t sa = (uint32_t)__cvta_generic_to_shared(s);
    asm volatile("cp.async.cg.shared.global [%0], [%1], 16;" :: "r"(sa), "l"(g));
}
__device__ __forceinline__ void cpa_commit() { asm volatile("cp.async.commit_group;"); }
__device__ __forceinline__ void cpa_wait0()  { asm volatile("cp.async.wait_group 0;"); }
__device__ __forceinline__ void cpa_wait1()  { asm volatile("cp.async.wait_group 1;"); }
__device__ __forceinline__ void cpa_wait2()  { asm volatile("cp.async.wait_group 2;"); }
__device__ __forceinline__ uint32_t smem_u32(const void* p) {
    return (uint32_t)__cvta_generic_to_shared(p);
}

// ---------------------------------------------------------------------------
// Phase 0: fused fp32 -> fp16 conversion; ONE float4 per thread (grid MUST be
// 8192 x 256 = 2097152 threads) for maximal chip-wide MLP. Wq pre-scaled.
// ---------------------------------------------------------------------------
#define SCL_F 0.1803368801111204f        // 0.125 * log2(e)
#define N4_X ((B_ * S_ * D_) / 4)        // 1048576
#define N4_W ((D_ * D_) / 4)             // 262144 == 2^18

__global__ __launch_bounds__(256) void to_half_all_kernel(
    const float* __restrict__ X,  const float* __restrict__ Wq,
    const float* __restrict__ Wk, const float* __restrict__ Wv,
    const float* __restrict__ Wo) {
    const int i = blockIdx.x * 256 + threadIdx.x;   // 0..2097151
    if (i == 0) { g_cnt_qkv = 0; g_cnt_fl = 0; }

    const float* src;
    __half* dst;
    float scl = 1.f;
    if (i < N4_X) {
        src = X + 4 * (size_t)i;
        dst = g_Xh + 4 * (size_t)i;
    } else {
        int k = i - N4_X;
        int w = k >> 18;
        int j = k & (N4_W - 1);
        const float* ws[4] = {Wq, Wk, Wv, Wo};
        __half* ds[4] = {g_Wqh, g_Wkh, g_Wvh, g_Woh};
        src = ws[w] + 4 * (size_t)j;
        dst = ds[w] + 4 * (size_t)j;
        if (w == 0) scl = SCL_F;        // fold softmax scale into Wq
    }
    float4 v = *(const float4*)src;
    __half2* d2 = (__half2*)dst;
    d2[0] = __floats2half2_rn(v.x * scl, v.y * scl);
    d2[1] = __floats2half2_rn(v.z * scl, v.w * scl);
}

// ---------------------------------------------------------------------------
// fp16 NT GEMM tile body: C[bm:+128, bn:+128] = A @ B^T (+bias). BK=64,
// 3-stage cp.async pipeline, 256 threads, 8 warps of 64x32, ldmatrix.
// Drains all cp.async groups; caller syncs before smem reuse.
// ---------------------------------------------------------------------------
#define GROWB 144                       // bytes per padded smem row
#define G_STG (128 * GROWB)             // 18432 B per operand stage
#define G_NBUF 3
#define GH_SMEM_BYTES (2 * G_NBUF * G_STG)   // 110592

template <bool HALF_OUT, bool BIAS>
__device__ __forceinline__ void gemm_tile(const __half* __restrict__ A,
                                          const __half* __restrict__ Bm,
                                          void* __restrict__ Cv,
                                          const float* __restrict__ bias,
                                          int N, int K, int bm, int bn) {
    extern __shared__ __align__(128) uint8_t dsm[];
    const int tid  = threadIdx.x;
    const int warp = tid >> 5;
    const int lane = tid & 31;
    const int g    = lane >> 2;
    const int t    = lane & 3;
    const int wm   = (warp >> 2) * 64;
    const int wn   = (warp & 3) * 32;

    const uint32_t smb = smem_u32(dsm);

    const int ar = (lane & 7) + 8 * ((lane >> 3) & 1);
    const int am = (lane >> 4);
    const int bmm = lane >> 3;
    const int br = ((bmm >> 1) << 3) + (lane & 7);
    const int bc = (bmm & 1);

    float acc[4][4][4];
#pragma unroll
    for (int i = 0; i < 4; i++)
#pragma unroll
        for (int j = 0; j < 4; j++)
#pragma unroll
            for (int v = 0; v < 4; v++) acc[i][j][v] = 0.f;

    const int lrow = tid >> 3;
    const int lc   = tid & 7;

    auto stage_copy = [&](int s) {
        const int buf = s % G_NBUF;
        const int k0 = 64 * s;
#pragma unroll
        for (int i = 0; i < 4; i++) {
            int row = lrow + 32 * i;
            cpa16(dsm + buf * G_STG + row * GROWB + lc * 16,
                  A + (size_t)(bm + row) * K + k0 + lc * 8);
            cpa16(dsm + G_NBUF * G_STG + buf * G_STG + row * GROWB + lc * 16,
                  Bm + (size_t)(bn + row) * K + k0 + lc * 8);
        }
        cpa_commit();
    };

    const int niter = K / 64;           // 16
    stage_copy(0); stage_copy(1);

    for (int it = 0; it < niter; it++) {
        const int buf = it % G_NBUF;
        if (it + 1 < niter) cpa_wait1(); else cpa_wait0();
        __syncthreads();
        if (it + 2 < niter) stage_copy(it + 2);

        const uint32_t Ab = smb + buf * G_STG;
        const uint32_t Bb = smb + G_NBUF * G_STG + buf * G_STG;
#pragma unroll
        for (int kk = 0; kk < 4; kk++) {
            uint32_t af[4][4], bf[4][2];
#pragma unroll
            for (int im = 0; im < 4; im++)
                ldm_x4(af[im], Ab + (wm + 16 * im + ar) * GROWB + (2 * kk + am) * 16);
#pragma unroll
            for (int j2 = 0; j2 < 2; j2++) {
                uint32_t r[4];
                ldm_x4(r, Bb + (wn + 16 * j2 + br) * GROWB + (2 * kk + bc) * 16);
                bf[2 * j2][0] = r[0]; bf[2 * j2][1] = r[1];
                bf[2 * j2 + 1][0] = r[2]; bf[2 * j2 + 1][1] = r[3];
            }
#pragma unroll
            for (int im = 0; im < 4; im++)
#pragma unroll
                for (int jn = 0; jn < 4; jn++)
                    mma16(acc[im][jn], af[im], bf[jn]);
        }
    }

#pragma unroll
    for (int im = 0; im < 4; im++) {
        int r0 = bm + wm + 16 * im + g;
#pragma unroll
        for (int jn = 0; jn < 4; jn++) {
            int c0 = bn + wn + 8 * jn + 2 * t;
            float v0 = acc[im][jn][0], v1 = acc[im][jn][1];
            float v2 = acc[im][jn][2], v3 = acc[im][jn][3];
            if (BIAS) {
                float bx = bias[c0], by = bias[c0 + 1];
                v0 += bx; v1 += by; v2 += bx; v3 += by;
            }
            if (HALF_OUT) {
                __half* C = (__half*)Cv;
                *(__half2*)(C + (size_t)r0 * N + c0) = __floats2half2_rn(v0, v1);
                *(__half2*)(C + (size_t)(r0 + 8) * N + c0) = __floats2half2_rn(v2, v3);
            } else {
                float* C = (float*)Cv;
                float2 w0 = {v0, v1}, w1 = {v2, v3};
                *(float2*)(C + (size_t)r0 * N + c0) = w0;
                *(float2*)(C + (size_t)(r0 + 8) * N + c0) = w1;
            }
        }
    }
}

// Persistent QKV GEMM: 768 tiles; z-fast tickets (X tile L2-hot across weights).
__global__ __launch_bounds__(256, 2) void gemm_qkv_kernel() {
    __shared__ int s_t;
    for (;;) {
        if (threadIdx.x == 0) s_t = atomicAdd(&g_cnt_qkv, 1);
        __syncthreads();
        const int t = s_t;
        if (t >= 768) return;
        const int z = t % 3;
        const int r = t / 3;
        const int bm = (r >> 3) * 128;
        const int bn = (r & 7) * 128;
        const __half* W = (z == 0) ? g_Wqh : (z == 1) ? g_Wkh : g_Wvh;
        __half* C = (z == 0) ? g_Q : (z == 1) ? g_K : g_V;
        gemm_tile<true, false>(g_Xh, W, C, nullptr, D_, D_, bm, bn);
        __syncthreads();
    }
}

__global__ __launch_bounds__(256, 2) void gemm_out_kernel(
    const float* __restrict__ bo, float* __restrict__ out) {
    gemm_tile<false, true>(g_ctx, g_Woh, out, bo, D_, D_,
                           blockIdx.y * 128, blockIdx.x * 128);
}

// ---------------------------------------------------------------------------
// Flash attention (persistent). Tile = (b, h, 128-row q tile); 8 warps; warp
// owns 16 q-rows. 3-stage K/V cp.async ring; Q first (wait2 gates fragments).
// Softmax: d = s - m in fp32, ex2.approx.f16x2 -> P fragments directly.
// Warps 0-3 skip final masked tile. Heavy-qt-first tickets.
// ---------------------------------------------------------------------------
#define FROWB 144
#define FQ_BYTES (128 * FROWB)          // 18432
#define FKV_BYTES (64 * FROWB)          // 9216
#define F_NBUF 3
#define FL_SMEM_BYTES (FQ_BYTES + 2 * F_NBUF * FKV_BYTES)   // 73728
#define NQT (S_ / 128)                  // 16
#define FL_TILES (NQT * H_ * B_)        // 512

__global__ __launch_bounds__(256, 2) void flash_kernel() {
    extern __shared__ __align__(128) uint8_t fsm[];
    uint8_t* Qs = fsm;
    uint8_t* Ks = fsm + FQ_BYTES;
    uint8_t* Vs = fsm + FQ_BYTES + F_NBUF * FKV_BYTES;

    __shared__ int s_t;

    const int tid  = threadIdx.x;
    const int warp = tid >> 5;
    const int lane = tid & 31;
    const int g    = lane >> 2;
    const int t    = lane & 3;
    const int wrow = warp * 16;

    const int ar = (lane & 7) + 8 * ((lane >> 3) & 1);
    const int am = (lane >> 4);
    const int bmm = lane >> 3;
    const int br = ((bmm >> 1) << 3) + (lane & 7);
    const int bc = (bmm & 1);
    const int vr = ((bmm & 1) << 3) + (lane & 7);
    const int vc = (bmm >> 1);

    const int krow = tid >> 3;
    const int kc   = tid & 7;

    for (;;) {
        if (tid == 0) s_t = atomicAdd(&g_cnt_fl, 1);
        __syncthreads();
        const int tk = s_t;
        if (tk >= FL_TILES) return;

        const int qt = NQT - 1 - (tk >> 5);     // heavy first
        const int hb = tk & 31;
        const int h  = hb & 15;
        const int b  = hb >> 4;
        const int q0 = qt * 128;
        const size_t base = (size_t)b * S_ * D_ + (size_t)h * HD_;

        auto copy_kv = [&](int s) {
            const int buf = s % F_NBUF;
            const int k0 = 64 * s;
#pragma unroll
            for (int i = 0; i < 2; i++) {
                int r = krow + 32 * i;
                cpa16(Ks + buf * FKV_BYTES + r * FROWB + kc * 16,
                      g_K + base + (size_t)(k0 + r) * D_ + kc * 8);
                cpa16(Vs + buf * FKV_BYTES + r * FROWB + kc * 16,
                      g_V + base + (size_t)(k0 + r) * D_ + kc * 8);
            }
            cpa_commit();
        };

        const int nkt = 2 * qt + 2;

        // Q copy first (own commit group), then two K/V stages.
#pragma unroll
        for (int i = 0; i < 4; i++) {
            int r = krow + 32 * i;
            cpa16(Qs + r * FROWB + kc * 16,
                  g_Q + base + (size_t)(q0 + r) * D_ + kc * 8);
        }
        cpa_commit();
        copy_kv(0);
        copy_kv(1);

        cpa_wait2();
        __syncthreads();
        const uint32_t Qb32 = smem_u32(Qs);
        uint32_t qa[4][4];
#pragma unroll
        for (int kk = 0; kk < 4; kk++)
            ldm_x4(qa[kk], Qb32 + (wrow + ar) * FROWB + (2 * kk + am) * 16);

        float o[8][4];
#pragma unroll
        for (int nn = 0; nn < 8; nn++)
#pragma unroll
            for (int v = 0; v < 4; v++) o[nn][v] = 0.f;
        float m0 = -CUDART_INF_F, m1 = -CUDART_INF_F;
        float l0 = 0.f, l1 = 0.f;

        for (int kt = 0; kt < nkt; kt++) {
            const int k0 = kt * 64;
            const bool diag = (kt >= 2 * qt);
            const int buf = kt % F_NBUF;

            if (kt + 1 < nkt) cpa_wait1(); else cpa_wait0();
            __syncthreads();
            if (kt + 2 < nkt) copy_kv(kt + 2);

            if (kt == 2 * qt + 1 && warp < 4) continue;

            const uint32_t Kb = smem_u32(Ks + buf * FKV_BYTES);
            const uint32_t Vb = smem_u32(Vs + buf * FKV_BYTES);

            float sc[8][4];
#pragma unroll
            for (int nn = 0; nn < 8; nn++)
#pragma unroll
                for (int v = 0; v < 4; v++) sc[nn][v] = 0.f;

#pragma unroll
            for (int kk = 0; kk < 4; kk++) {
#pragma unroll
                for (int j2 = 0; j2 < 4; j2++) {
                    uint32_t r[4];
                    ldm_x4(r, Kb + (16 * j2 + br) * FROWB + (2 * kk + bc) * 16);
                    mma16(sc[2 * j2], qa[kk], &r[0]);
                    mma16(sc[2 * j2 + 1], qa[kk], &r[2]);
                }
            }

            const int gr0 = q0 + wrow + g;
            const int gr1 = gr0 + 8;
            float mx0 = -CUDART_INF_F, mx1 = -CUDART_INF_F;
#pragma unroll
            for (int nn = 0; nn < 8; nn++) {
                if (diag) {
                    int c0 = k0 + 8 * nn + 2 * t;
                    if (c0 > gr0)     sc[nn][0] = -CUDART_INF_F;
                    if (c0 + 1 > gr0) sc[nn][1] = -CUDART_INF_F;
                    if (c0 > gr1)     sc[nn][2] = -CUDART_INF_F;
                    if (c0 + 1 > gr1) sc[nn][3] = -CUDART_INF_F;
                }
                mx0 = fmaxf(mx0, fmaxf(sc[nn][0], sc[nn][1]));
                mx1 = fmaxf(mx1, fmaxf(sc[nn][2], sc[nn][3]));
            }
            mx0 = fmaxf(mx0, __shfl_xor_sync(0xffffffffu, mx0, 1));
            mx0 = fmaxf(mx0, __shfl_xor_sync(0xffffffffu, mx0, 2));
            mx1 = fmaxf(mx1, __shfl_xor_sync(0xffffffffu, mx1, 1));
            mx1 = fmaxf(mx1, __shfl_xor_sync(0xffffffffu, mx1, 2));

            float mn0 = fmaxf(m0, mx0);
            float mn1 = fmaxf(m1, mx1);
            float corr0 = ex2(m0 - mn0);
            float corr1 = ex2(m1 - mn1);
            m0 = mn0; m1 = mn1;

            // p = 2^(s-m): pack fp32 diffs to half2, one f16x2 ex2 per pair.
            // Results are EXACTLY the PV A-operand fragments (fp16 pairs).
            uint32_t pp[8][2];
            float sum0 = 0.f, sum1 = 0.f;
#pragma unroll
            for (int nn = 0; nn < 8; nn++) {
                pp[nn][0] = ex2h2(packh2(sc[nn][0] - mn0, sc[nn][1] - mn0));
                pp[nn][1] = ex2h2(packh2(sc[nn][2] - mn1, sc[nn][3] - mn1));
                float2 f0 = __half22float2(*(__half2*)&pp[nn][0]);
                float2 f1 = __half22float2(*(__half2*)&pp[nn][1]);
                sum0 += f0.x + f0.y;
                sum1 += f1.x + f1.y;
            }
            sum0 += __shfl_xor_sync(0xffffffffu, sum0, 1);
            sum0 += __shfl_xor_sync(0xffffffffu, sum0, 2);
            sum1 += __shfl_xor_sync(0xffffffffu, sum1, 1);
            sum1 += __shfl_xor_sync(0xffffffffu, sum1, 2);
            l0 = l0 * corr0 + sum0;
            l1 = l1 * corr1 + sum1;

#pragma unroll
            for (int nn = 0; nn < 8; nn++) {
                o[nn][0] *= corr0; o[nn][1] *= corr0;
                o[nn][2] *= corr1; o[nn][3] *= corr1;
            }

#pragma unroll
            for (int kb = 0; kb < 4; kb++) {
                uint32_t pa[4];
                pa[0] = pp[2 * kb][0];
                pa[1] = pp[2 * kb][1];
                pa[2] = pp[2 * kb + 1][0];
                pa[3] = pp[2 * kb + 1][1];
#pragma unroll
                for (int j2 = 0; j2 < 4; j2++) {
                    uint32_t r[4];
                    ldm_x4_t(r, Vb + (16 * kb + vr) * FROWB + (2 * j2 + vc) * 16);
                    mma16(o[2 * j2], pa, &r[0]);
                    mma16(o[2 * j2 + 1], pa, &r[2]);
                }
            }
        }

        const float inv0 = 1.f / l0;
        const float inv1 = 1.f / l1;
        const int gr0 = q0 + wrow + g;
#pragma unroll
        for (int nn = 0; nn < 8; nn++) {
            int c = 8 * nn + 2 * t;
            *(__half2*)&g_ctx[base + (size_t)gr0 * D_ + c] =
                __floats2half2_rn(o[nn][0] * inv0, o[nn][1] * inv0);
            *(__half2*)&g_ctx[base + (size_t)(gr0 + 8) * D_ + c] =
                __floats2half2_rn(o[nn][2] * inv1, o[nn][3] * inv1);
        }
        __syncthreads();
    }
}

// ---------------------------------------------------------------------------
extern "C" void kernel_launch(void* const* d_in, const int* in_sizes, int n_in,
                              void* d_out, int out_size) {
    const float* X  = (const float*)d_in[0];
    const float* Wq = (const float*)d_in[1];
    const float* Wk = (const float*)d_in[2];
    const float* Wv = (const float*)d_in[3];
    const float* Wo = (const float*)d_in[4];
    const float* bo = (const float*)d_in[5];
    float* out = (float*)d_out;
    (void)in_sizes; (void)n_in; (void)out_size;

    static bool attr_done = false;
    if (!attr_done) {
        cudaFuncSetAttribute(flash_kernel,
                             cudaFuncAttributeMaxDynamicSharedMemorySize,
                             FL_SMEM_BYTES);
        cudaFuncSetAttribute(gemm_qkv_kernel,
                             cudaFuncAttributeMaxDynamicSharedMemorySize,
                             GH_SMEM_BYTES);
        cudaFuncSetAttribute(gemm_out_kernel,
                             cudaFuncAttributeMaxDynamicSharedMemorySize,
                             GH_SMEM_BYTES);
        attr_done = true;
    }

    // Phase 0: conversion + ticket reset (grid MUST be 8192 x 256)
    to_half_all_kernel<<<8192, 256>>>(X, Wq, Wk, Wv, Wo);

    // Phase 1: persistent QKV projections
    gemm_qkv_kernel<<<PERS_CTAS, 256, GH_SMEM_BYTES>>>();

    // Phase 2: persistent flash attention
    flash_kernel<<<PERS_CTAS, 256, FL_SMEM_BYTES>>>();

    {   // Phase 3: output projection + bias (one wave)
        dim3 grid(D_ / 128, (B_ * S_) / 128, 1);
        gemm_out_kernel<<<grid, 256, GH_SMEM_BYTES>>>(bo, out);
    }
}

// round 17
// speedup vs baseline: 1.0471x; 1.0471x over previous
#include <cuda_runtime.h>
#include <cuda_fp16.h>
#include <math_constants.h>
#include <cstdint>

// ---------------------------------------------------------------------------
// MultiHeadAttention fp32 I/O, fp16 tensor-core compute (fp32 accumulate).
// B=2, S=2048, D=1024, H=16, Hd=64, causal.   [exact R13 best configuration]
//  Phase 0: ONE fused convert (static 8-way unroll, resets ticket counters)
//  Phase 1: Q/K/V = X @ W^T     (persistent fp16 GEMM, dynamic tile tickets)
//  Phase 2: flash attention      (persistent, heavy-first dynamic tickets)
//  Phase 3: out = ctx @ Wo^T + b (plain fp16 GEMM, 256 tiles < slots)
// ---------------------------------------------------------------------------

#define B_   2
#define S_   2048
#define D_   1024
#define H_   16
#define HD_  64

__device__ __half g_Q[B_ * S_ * D_];
__device__ __half g_K[B_ * S_ * D_];
__device__ __half g_V[B_ * S_ * D_];
__device__ __half g_ctx[B_ * S_ * D_];
__device__ __half g_Xh[B_ * S_ * D_];
__device__ __half g_Wqh[D_ * D_];
__device__ __half g_Wkh[D_ * D_];
__device__ __half g_Wvh[D_ * D_];
__device__ __half g_Woh[D_ * D_];

__device__ int g_cnt_qkv;
__device__ int g_cnt_fl;

#define PERS_CTAS 296                   // 148 SMs x 2 CTAs

// --------------------------- helpers ---------------------------------------
__device__ __forceinline__ float ex2(float x) {
    float r;
    asm("ex2.approx.ftz.f32 %0, %1;" : "=f"(r) : "f"(x));
    return r;
}
__device__ __forceinline__ uint32_t packh2(float lo, float hi) {
    uint32_t d;
    asm("cvt.rn.f16x2.f32 %0, %1, %2;" : "=r"(d) : "f"(hi), "f"(lo));
    return d;
}
__device__ __forceinline__ void mma16(float* c, const uint32_t* a, const uint32_t* b) {
    asm volatile(
        "mma.sync.aligned.m16n8k16.row.col.f32.f16.f16.f32 "
        "{%0,%1,%2,%3}, {%4,%5,%6,%7}, {%8,%9}, {%0,%1,%2,%3};\n"
        : "+f"(c[0]), "+f"(c[1]), "+f"(c[2]), "+f"(c[3])
        : "r"(a[0]), "r"(a[1]), "r"(a[2]), "r"(a[3]), "r"(b[0]), "r"(b[1]));
}
__device__ __forceinline__ void ldm_x4(uint32_t* r, uint32_t addr) {
    asm volatile("ldmatrix.sync.aligned.m8n8.x4.shared.b16 {%0,%1,%2,%3}, [%4];"
                 : "=r"(r[0]), "=r"(r[1]), "=r"(r[2]), "=r"(r[3]) : "r"(addr));
}
__device__ __forceinline__ void ldm_x4_t(uint32_t* r, uint32_t addr) {
    asm volatile("ldmatrix.sync.aligned.m8n8.x4.trans.shared.b16 {%0,%1,%2,%3}, [%4];"
                 : "=r"(r[0]), "=r"(r[1]), "=r"(r[2]), "=r"(r[3]) : "r"(addr));
}
__device__ __forceinline__ void cpa16(void* s, const void* g) {
    uint32_t sa = (uint32_t)__cvta_generic_to_shared(s);
    asm volatile("cp.async.cg.shared.global [%0], [%1], 16;" :: "r"(sa), "l"(g));
}
__device__ __forceinline__ void cpa_commit() { asm volatile("cp.async.commit_group;"); }
__device__ __forceinline__ void cpa_wait0()  { asm volatile("cp.async.wait_group 0;"); }
__device__ __forceinline__ void cpa_wait1()  { asm volatile("cp.async.wait_group 1;"); }
__device__ __forceinline__ void cpa_wait2()  { asm volatile("cp.async.wait_group 2;"); }
__device__ __forceinline__ uint32_t smem_u32(const void* p) {
    return (uint32_t)__cvta_generic_to_shared(p);
}

// ---------------------------------------------------------------------------
// Phase 0: fused fp32 -> fp16 conversion; static 8-way unroll (grid 1024x256).
// Also resets the persistent-kernel ticket counters.
// ---------------------------------------------------------------------------
#define SCL_F 0.1803368801111204f        // 0.125 * log2(e)
#define CVT_CHUNK 262144                  // 2^18 float4 per slice

__global__ __launch_bounds__(256) void to_half_all_kernel(
    const float* __restrict__ X,  const float* __restrict__ Wq,
    const float* __restrict__ Wk, const float* __restrict__ Wv,
    const float* __restrict__ Wo) {
    if (blockIdx.x == 0 && threadIdx.x == 0) {
        g_cnt_qkv = 0;
        g_cnt_fl = 0;
    }
    const int idx = blockIdx.x * 256 + threadIdx.x;     // 0..262143
    const size_t o = 4 * (size_t)idx;
    const size_t st = 4 * (size_t)CVT_CHUNK;

    float4 v[8];
    v[0] = *(const float4*)(X + o);
    v[1] = *(const float4*)(X + o + st);
    v[2] = *(const float4*)(X + o + 2 * st);
    v[3] = *(const float4*)(X + o + 3 * st);
    v[4] = *(const float4*)(Wq + o);
    v[5] = *(const float4*)(Wk + o);
    v[6] = *(const float4*)(Wv + o);
    v[7] = *(const float4*)(Wo + o);

    v[4].x *= SCL_F; v[4].y *= SCL_F; v[4].z *= SCL_F; v[4].w *= SCL_F;

    __half2* dx = (__half2*)(g_Xh + o);
    dx[0] = __floats2half2_rn(v[0].x, v[0].y);
    dx[1] = __floats2half2_rn(v[0].z, v[0].w);
    dx = (__half2*)(g_Xh + o + st);
    dx[0] = __floats2half2_rn(v[1].x, v[1].y);
    dx[1] = __floats2half2_rn(v[1].z, v[1].w);
    dx = (__half2*)(g_Xh + o + 2 * st);
    dx[0] = __floats2half2_rn(v[2].x, v[2].y);
    dx[1] = __floats2half2_rn(v[2].z, v[2].w);
    dx = (__half2*)(g_Xh + o + 3 * st);
    dx[0] = __floats2half2_rn(v[3].x, v[3].y);
    dx[1] = __floats2half2_rn(v[3].z, v[3].w);

    __half2* dw = (__half2*)(g_Wqh + o);
    dw[0] = __floats2half2_rn(v[4].x, v[4].y);
    dw[1] = __floats2half2_rn(v[4].z, v[4].w);
    dw = (__half2*)(g_Wkh + o);
    dw[0] = __floats2half2_rn(v[5].x, v[5].y);
    dw[1] = __floats2half2_rn(v[5].z, v[5].w);
    dw = (__half2*)(g_Wvh + o);
    dw[0] = __floats2half2_rn(v[6].x, v[6].y);
    dw[1] = __floats2half2_rn(v[6].z, v[6].w);
    dw = (__half2*)(g_Woh + o);
    dw[0] = __floats2half2_rn(v[7].x, v[7].y);
    dw[1] = __floats2half2_rn(v[7].z, v[7].w);
}

// ---------------------------------------------------------------------------
// fp16 NT GEMM tile body: C[bm:bm+128, bn:bn+128] = A @ B^T (+bias).
// BK=64, 3-stage cp.async pipeline, 256 threads, 8 warps of 64x32, ldmatrix.
// Ends with all cp.async groups drained; caller must __syncthreads() before
// reusing smem for another tile.
// ---------------------------------------------------------------------------
#define GROWB 144                       // bytes per padded smem row
#define G_STG (128 * GROWB)             // 18432 B per operand stage
#define G_NBUF 3
#define GH_SMEM_BYTES (2 * G_NBUF * G_STG)   // 110592

template <bool HALF_OUT, bool BIAS>
__device__ __forceinline__ void gemm_tile(const __half* __restrict__ A,
                                          const __half* __restrict__ Bm,
                                          void* __restrict__ Cv,
                                          const float* __restrict__ bias,
                                          int N, int K, int bm, int bn) {
    extern __shared__ __align__(128) uint8_t dsm[];
    const int tid  = threadIdx.x;
    const int warp = tid >> 5;
    const int lane = tid & 31;
    const int g    = lane >> 2;
    const int t    = lane & 3;
    const int wm   = (warp >> 2) * 64;
    const int wn   = (warp & 3) * 32;

    const uint32_t smb = smem_u32(dsm);

    const int ar = (lane & 7) + 8 * ((lane >> 3) & 1);  // A row-within-16
    const int am = (lane >> 4);                         // A chunk sel
    const int bmm = lane >> 3;                          // B matrix id
    const int br = ((bmm >> 1) << 3) + (lane & 7);      // B row-within-16
    const int bc = (bmm & 1);                           // B chunk sel

    float acc[4][4][4];
#pragma unroll
    for (int i = 0; i < 4; i++)
#pragma unroll
        for (int j = 0; j < 4; j++)
#pragma unroll
            for (int v = 0; v < 4; v++) acc[i][j][v] = 0.f;

    const int lrow = tid >> 3;          // 0..31 (+32*i)
    const int lc   = tid & 7;           // chunk 0..7 (16B each)

    auto stage_copy = [&](int s) {
        const int buf = s % G_NBUF;
        const int k0 = 64 * s;
#pragma unroll
        for (int i = 0; i < 4; i++) {
            int row = lrow + 32 * i;
            cpa16(dsm + buf * G_STG + row * GROWB + lc * 16,
                  A + (size_t)(bm + row) * K + k0 + lc * 8);
            cpa16(dsm + G_NBUF * G_STG + buf * G_STG + row * GROWB + lc * 16,
                  Bm + (size_t)(bn + row) * K + k0 + lc * 8);
        }
        cpa_commit();
    };

    const int niter = K / 64;           // 16
    stage_copy(0); stage_copy(1);

    for (int it = 0; it < niter; it++) {
        const int buf = it % G_NBUF;
        if (it + 1 < niter) cpa_wait1(); else cpa_wait0();
        __syncthreads();
        if (it + 2 < niter) stage_copy(it + 2);

        const uint32_t Ab = smb + buf * G_STG;
        const uint32_t Bb = smb + G_NBUF * G_STG + buf * G_STG;
#pragma unroll
        for (int kk = 0; kk < 4; kk++) {
            uint32_t af[4][4], bf[4][2];
#pragma unroll
            for (int im = 0; im < 4; im++)
                ldm_x4(af[im], Ab + (wm + 16 * im + ar) * GROWB + (2 * kk + am) * 16);
#pragma unroll
            for (int j2 = 0; j2 < 2; j2++) {
                uint32_t r[4];
                ldm_x4(r, Bb + (wn + 16 * j2 + br) * GROWB + (2 * kk + bc) * 16);
                bf[2 * j2][0] = r[0]; bf[2 * j2][1] = r[1];
                bf[2 * j2 + 1][0] = r[2]; bf[2 * j2 + 1][1] = r[3];
            }
#pragma unroll
            for (int im = 0; im < 4; im++)
#pragma unroll
                for (int jn = 0; jn < 4; jn++)
                    mma16(acc[im][jn], af[im], bf[jn]);
        }
    }

#pragma unroll
    for (int im = 0; im < 4; im++) {
        int r0 = bm + wm + 16 * im + g;
#pragma unroll
        for (int jn = 0; jn < 4; jn++) {
            int c0 = bn + wn + 8 * jn + 2 * t;
            float v0 = acc[im][jn][0], v1 = acc[im][jn][1];
            float v2 = acc[im][jn][2], v3 = acc[im][jn][3];
            if (BIAS) {
                float bx = bias[c0], by = bias[c0 + 1];
                v0 += bx; v1 += by; v2 += bx; v3 += by;
            }
            if (HALF_OUT) {
                __half* C = (__half*)Cv;
                *(__half2*)(C + (size_t)r0 * N + c0) = __floats2half2_rn(v0, v1);
                *(__half2*)(C + (size_t)(r0 + 8) * N + c0) = __floats2half2_rn(v2, v3);
            } else {
                float* C = (float*)Cv;
                float2 w0 = {v0, v1}, w1 = {v2, v3};
                *(float2*)(C + (size_t)r0 * N + c0) = w0;
                *(float2*)(C + (size_t)(r0 + 8) * N + c0) = w1;
            }
        }
    }
}

// Persistent QKV GEMM: 768 tiles (3 weights x 32 M x 8 N) via ticket counter.
__global__ __launch_bounds__(256, 2) void gemm_qkv_kernel() {
    __shared__ int s_t;
    for (;;) {
        if (threadIdx.x == 0) s_t = atomicAdd(&g_cnt_qkv, 1);
        __syncthreads();
        const int t = s_t;
        if (t >= 768) return;
        const int z = t >> 8;           // weight select
        const int r = t & 255;
        const int bm = (r >> 3) * 128;
        const int bn = (r & 7) * 128;
        const __half* W = (z == 0) ? g_Wqh : (z == 1) ? g_Wkh : g_Wvh;
        __half* C = (z == 0) ? g_Q : (z == 1) ? g_K : g_V;
        gemm_tile<true, false>(g_Xh, W, C, nullptr, D_, D_, bm, bn);
        __syncthreads();                // smem + s_t reuse guard
    }
}

// Plain out-proj GEMM (256 tiles fit in one wave of resident CTAs).
__global__ __launch_bounds__(256, 2) void gemm_out_kernel(
    const float* __restrict__ bo, float* __restrict__ out) {
    gemm_tile<false, true>(g_ctx, g_Woh, out, bo, D_, D_,
                           blockIdx.y * 128, blockIdx.x * 128);
}

// ---------------------------------------------------------------------------
// Flash attention (persistent). Tile = (b, h, 128-row q tile); 8 warps; warp
// owns 16 q-rows. 3-stage K/V cp.async ring; Q first (wait2 gates fragments).
// P in registers; warps 0-3 skip final masked tile. Heavy-qt-first tickets.
// ---------------------------------------------------------------------------
#define FROWB 144
#define FQ_BYTES (128 * FROWB)          // 18432
#define FKV_BYTES (64 * FROWB)          // 9216
#define F_NBUF 3
#define FL_SMEM_BYTES (FQ_BYTES + 2 * F_NBUF * FKV_BYTES)   // 73728
#define NQT (S_ / 128)                  // 16
#define FL_TILES (NQT * H_ * B_)        // 512

__global__ __launch_bounds__(256, 2) void flash_kernel() {
    extern __shared__ __align__(128) uint8_t fsm[];
    uint8_t* Qs = fsm;
    uint8_t* Ks = fsm + FQ_BYTES;
    uint8_t* Vs = fsm + FQ_BYTES + F_NBUF * FKV_BYTES;

    __shared__ int s_t;

    const int tid  = threadIdx.x;
    const int warp = tid >> 5;
    const int lane = tid & 31;
    const int g    = lane >> 2;
    const int t    = lane & 3;
    const int wrow = warp * 16;

    const int ar = (lane & 7) + 8 * ((lane >> 3) & 1);
    const int am = (lane >> 4);
    const int bmm = lane >> 3;
    const int br = ((bmm >> 1) << 3) + (lane & 7);
    const int bc = (bmm & 1);
    const int vr = ((bmm & 1) << 3) + (lane & 7);
    const int vc = (bmm >> 1);

    const int krow = tid >> 3;
    const int kc   = tid & 7;

    for (;;) {
        if (tid == 0) s_t = atomicAdd(&g_cnt_fl, 1);
        __syncthreads();
        const int tk = s_t;
        if (tk >= FL_TILES) return;

        // heavy first: qt descending
        const int qt = NQT - 1 - (tk >> 5);
        const int hb = tk & 31;
        const int h  = hb & 15;
        const int b  = hb >> 4;
        const int q0 = qt * 128;
        const size_t base = (size_t)b * S_ * D_ + (size_t)h * HD_;

        auto copy_kv = [&](int s) {
            const int buf = s % F_NBUF;
            const int k0 = 64 * s;
#pragma unroll
            for (int i = 0; i < 2; i++) {
                int r = krow + 32 * i;
                cpa16(Ks + buf * FKV_BYTES + r * FROWB + kc * 16,
                      g_K + base + (size_t)(k0 + r) * D_ + kc * 8);
                cpa16(Vs + buf * FKV_BYTES + r * FROWB + kc * 16,
                      g_V + base + (size_t)(k0 + r) * D_ + kc * 8);
            }
            cpa_commit();
        };

        const int nkt = 2 * qt + 2;

        // Q copy first (own commit group), then two K/V stages.
#pragma unroll
        for (int i = 0; i < 4; i++) {
            int r = krow + 32 * i;
            cpa16(Qs + r * FROWB + kc * 16,
                  g_Q + base + (size_t)(q0 + r) * D_ + kc * 8);
        }
        cpa_commit();
        copy_kv(0);
        copy_kv(1);

        cpa_wait2();
        __syncthreads();
        const uint32_t Qb32 = smem_u32(Qs);
        uint32_t qa[4][4];
#pragma unroll
        for (int kk = 0; kk < 4; kk++)
            ldm_x4(qa[kk], Qb32 + (wrow + ar) * FROWB + (2 * kk + am) * 16);

        float o[8][4];
#pragma unroll
        for (int nn = 0; nn < 8; nn++)
#pragma unroll
            for (int v = 0; v < 4; v++) o[nn][v] = 0.f;
        float m0 = -CUDART_INF_F, m1 = -CUDART_INF_F;
        float l0 = 0.f, l1 = 0.f;

        for (int kt = 0; kt < nkt; kt++) {
            const int k0 = kt * 64;
            const bool diag = (kt >= 2 * qt);
            const int buf = kt % F_NBUF;

            if (kt + 1 < nkt) cpa_wait1(); else cpa_wait0();
            __syncthreads();
            if (kt + 2 < nkt) copy_kv(kt + 2);

            if (kt == 2 * qt + 1 && warp < 4) continue;

            const uint32_t Kb = smem_u32(Ks + buf * FKV_BYTES);
            const uint32_t Vb = smem_u32(Vs + buf * FKV_BYTES);

            float sc[8][4];
#pragma unroll
            for (int nn = 0; nn < 8; nn++)
#pragma unroll
                for (int v = 0; v < 4; v++) sc[nn][v] = 0.f;

#pragma unroll
            for (int kk = 0; kk < 4; kk++) {
#pragma unroll
                for (int j2 = 0; j2 < 4; j2++) {
                    uint32_t r[4];
                    ldm_x4(r, Kb + (16 * j2 + br) * FROWB + (2 * kk + bc) * 16);
                    mma16(sc[2 * j2], qa[kk], &r[0]);
                    mma16(sc[2 * j2 + 1], qa[kk], &r[2]);
                }
            }

            const int gr0 = q0 + wrow + g;
            const int gr1 = gr0 + 8;
            float mx0 = -CUDART_INF_F, mx1 = -CUDART_INF_F;
#pragma unroll
            for (int nn = 0; nn < 8; nn++) {
                if (diag) {
                    int c0 = k0 + 8 * nn + 2 * t;
                    if (c0 > gr0)     sc[nn][0] = -CUDART_INF_F;
                    if (c0 + 1 > gr0) sc[nn][1] = -CUDART_INF_F;
                    if (c0 > gr1)     sc[nn][2] = -CUDART_INF_F;
                    if (c0 + 1 > gr1) sc[nn][3] = -CUDART_INF_F;
                }
                mx0 = fmaxf(mx0, fmaxf(sc[nn][0], sc[nn][1]));
                mx1 = fmaxf(mx1, fmaxf(sc[nn][2], sc[nn][3]));
            }
            mx0 = fmaxf(mx0, __shfl_xor_sync(0xffffffffu, mx0, 1));
            mx0 = fmaxf(mx0, __shfl_xor_sync(0xffffffffu, mx0, 2));
            mx1 = fmaxf(mx1, __shfl_xor_sync(0xffffffffu, mx1, 1));
            mx1 = fmaxf(mx1, __shfl_xor_sync(0xffffffffu, mx1, 2));

            float mn0 = fmaxf(m0, mx0);
            float mn1 = fmaxf(m1, mx1);
            float corr0 = ex2(m0 - mn0);
            float corr1 = ex2(m1 - mn1);
            m0 = mn0; m1 = mn1;

            float sum0 = 0.f, sum1 = 0.f;
#pragma unroll
            for (int nn = 0; nn < 8; nn++) {
                float p0 = ex2(sc[nn][0] - mn0);
                float p1 = ex2(sc[nn][1] - mn0);
                float p2 = ex2(sc[nn][2] - mn1);
                float p3 = ex2(sc[nn][3] - mn1);
                sum0 += p0 + p1; sum1 += p2 + p3;
                sc[nn][0] = p0; sc[nn][1] = p1; sc[nn][2] = p2; sc[nn][3] = p3;
            }
            sum0 += __shfl_xor_sync(0xffffffffu, sum0, 1);
            sum0 += __shfl_xor_sync(0xffffffffu, sum0, 2);
            sum1 += __shfl_xor_sync(0xffffffffu, sum1, 1);
            sum1 += __shfl_xor_sync(0xffffffffu, sum1, 2);
            l0 = l0 * corr0 + sum0;
            l1 = l1 * corr1 + sum1;

#pragma unroll
            for (int nn = 0; nn < 8; nn++) {
                o[nn][0] *= corr0; o[nn][1] *= corr0;
                o[nn][2] *= corr1; o[nn][3] *= corr1;
            }

#pragma unroll
            for (int kb = 0; kb < 4; kb++) {
                uint32_t pa[4];
                pa[0] = packh2(sc[2 * kb][0],     sc[2 * kb][1]);
                pa[1] = packh2(sc[2 * kb][2],     sc[2 * kb][3]);
                pa[2] = packh2(sc[2 * kb + 1][0], sc[2 * kb + 1][1]);
                pa[3] = packh2(sc[2 * kb + 1][2], sc[2 * kb + 1][3]);
#pragma unroll
                for (int j2 = 0; j2 < 4; j2++) {
                    uint32_t r[4];
                    ldm_x4_t(r, Vb + (16 * kb + vr) * FROWB + (2 * j2 + vc) * 16);
                    mma16(o[2 * j2], pa, &r[0]);
                    mma16(o[2 * j2 + 1], pa, &r[2]);
                }
            }
        }

        const float inv0 = 1.f / l0;
        const float inv1 = 1.f / l1;
        const int gr0 = q0 + wrow + g;
#pragma unroll
        for (int nn = 0; nn < 8; nn++) {
            int c = 8 * nn + 2 * t;
            *(__half2*)&g_ctx[base + (size_t)gr0 * D_ + c] =
                __floats2half2_rn(o[nn][0] * inv0, o[nn][1] * inv0);
            *(__half2*)&g_ctx[base + (size_t)(gr0 + 8) * D_ + c] =
                __floats2half2_rn(o[nn][2] * inv1, o[nn][3] * inv1);
        }
        __syncthreads();                // smem + s_t reuse guard
    }
}

// ---------------------------------------------------------------------------
extern "C" void kernel_launch(void* const* d_in, const int* in_sizes, int n_in,
                              void* d_out, int out_size) {
    const float* X  = (const float*)d_in[0];
    const float* Wq = (const float*)d_in[1];
    const float* Wk = (const float*)d_in[2];
    const float* Wv = (const float*)d_in[3];
    const float* Wo = (const float*)d_in[4];
    const float* bo = (const float*)d_in[5];
    float* out = (float*)d_out;
    (void)in_sizes; (void)n_in; (void)out_size;

    static bool attr_done = false;
    if (!attr_done) {
        cudaFuncSetAttribute(flash_kernel,
                             cudaFuncAttributeMaxDynamicSharedMemorySize,
                             FL_SMEM_BYTES);
        cudaFuncSetAttribute(gemm_qkv_kernel,
                             cudaFuncAttributeMaxDynamicSharedMemorySize,
                             GH_SMEM_BYTES);
        cudaFuncSetAttribute(gemm_out_kernel,
                             cudaFuncAttributeMaxDynamicSharedMemorySize,
                             GH_SMEM_BYTES);
        attr_done = true;
    }

    // Phase 0: fused conversion + ticket reset (grid MUST be 1024 x 256)
    to_half_all_kernel<<<1024, 256>>>(X, Wq, Wk, Wv, Wo);

    // Phase 1: persistent QKV projections
    gemm_qkv_kernel<<<PERS_CTAS, 256, GH_SMEM_BYTES>>>();

    // Phase 2: persistent flash attention
    flash_kernel<<<PERS_CTAS, 256, FL_SMEM_BYTES>>>();

    {   // Phase 3: output projection + bias (one wave)
        dim3 grid(D_ / 128, (B_ * S_) / 128, 1);
        gemm_out_kernel<<<grid, 256, GH_SMEM_BYTES>>>(bo, out);
    }
}